// round 17
// baseline (speedup 1.0000x reference)
#include <cuda_runtime.h>
#include <cuda_fp16.h>
#include <cstdint>
#include <math.h>

#define NTOK   49
#define HEADS  6
#define DIM    192
#define DH     32
#define QSCALE 0.1767766952966369f

/* ================= device scratch (static: allocation-free) ================= */
__device__ __half  g_q16[200704u * 576u];   /* qkv out fp16 (q pre-scaled) 231 MB */
__device__ __half  g_wq[576 * 192];
__device__ __half  g_wp[192 * 192];
__device__ float   g_bias[HEADS * NTOK * NTOK];

__device__ __forceinline__ uint32_t hpack(__half a, __half b) {
    return (uint32_t)__half_as_ushort(a) | ((uint32_t)__half_as_ushort(b) << 16);
}

/* ================= prep: weights -> fp16 (RN), materialize bias ================= */
__global__ void prep_kernel(const float* __restrict__ qkv_w, const float* __restrict__ proj_w,
                            const float* __restrict__ bias_table, const int* __restrict__ rel_idx)
{
    int i = blockIdx.x * 256 + threadIdx.x;
    if (i < 576 * 192) g_wq[i] = __float2half_rn(qkv_w[i]);
    if (i < 192 * 192) g_wp[i] = __float2half_rn(proj_w[i]);
    if (i < HEADS * NTOK * NTOK) {
        int m = i % NTOK, t = i / NTOK;
        int n = t % NTOK, h = t / NTOK;
        g_bias[i] = bias_table[rel_idx[n * NTOK + m] * HEADS + h];
    }
}

/* ================= mma fp16 / cp.async ================= */
__device__ __forceinline__ void mma16816(float* c, const uint32_t* a, const uint32_t* b) {
    asm volatile(
        "mma.sync.aligned.m16n8k16.row.col.f32.f16.f16.f32 "
        "{%0,%1,%2,%3}, {%4,%5,%6,%7}, {%8,%9}, {%0,%1,%2,%3};"
        : "+f"(c[0]), "+f"(c[1]), "+f"(c[2]), "+f"(c[3])
        : "r"(a[0]), "r"(a[1]), "r"(a[2]), "r"(a[3]), "r"(b[0]), "r"(b[1]));
}
__device__ __forceinline__ void cp16(uint32_t dst, const void* src) {
    asm volatile("cp.async.cg.shared.global [%0], [%1], 16;" :: "r"(dst), "l"(src));
}

/* ================ K1: qkv GEMM (exact R16 — best measured) ================ */
#define APAD_B 400
#define A_H    0
#define B_BASE (128 * APAD_B)                   /* 51200 */
#define B_STEP 27648
#define GEMM_SMEM (B_BASE + 2 * B_STEP)         /* 106496 */

__global__ __launch_bounds__(256, 1)
void gemm_qkv(const float* __restrict__ A,
              const __half* __restrict__ B,
              const float* __restrict__ bias)
{
    extern __shared__ char smc[];
    uint32_t sb;
    asm("{ .reg .u64 t; cvta.to.shared.u64 t, %1; cvt.u32.u64 %0, t; }" : "=r"(sb) : "l"(smc));

    const int tid = threadIdx.x, wid = tid >> 5, lane = tid & 31;
    const int mtile = blockIdx.x;
    const int wm = (wid & 3) * 32;
    const int wn = (wid >> 2) * 96;

    auto prefetch = [&](int idx) {
        int nt2 = idx / 3, kc = idx - nt2 * 3;
        const __half* bp = B + (size_t)nt2 * 192 * 192 + kc * 64;
        uint32_t dst = sb + B_BASE + (idx & 1) * B_STEP;
        #pragma unroll
        for (int it = 0; it < 6; it++) {
            int g = tid + it * 256;
            int row = g >> 3, c8 = g & 7;
            cp16(dst + row * 144 + c8 * 16, bp + row * 192 + c8 * 8);
        }
        asm volatile("cp.async.commit_group;" ::: "memory");
    };

    prefetch(0);
    prefetch(1);

    {
        const float* Abase = A + (size_t)mtile * 128 * 192;
        #pragma unroll
        for (int it = 0; it < 24; it++) {
            int g = tid + it * 256;
            int row = g / 48, c4 = (g % 48) * 4;
            float4 f = *(const float4*)(Abase + row * 192 + c4);
            *(uint2*)(smc + A_H + row * APAD_B + c4 * 2) =
                make_uint2(hpack(__float2half_rn(f.x), __float2half_rn(f.y)),
                           hpack(__float2half_rn(f.z), __float2half_rn(f.w)));
        }
    }
    __syncthreads();

    float acc[2][12][4];

    for (int nt = 0; nt < 3; nt++) {
        #pragma unroll
        for (int mf = 0; mf < 2; mf++)
            #pragma unroll
            for (int nf = 0; nf < 12; nf++)
                #pragma unroll
                for (int j = 0; j < 4; j++) acc[mf][nf][j] = 0.f;

        for (int kc = 0; kc < 3; kc++) {
            const int idx = nt * 3 + kc;
            if (idx < 8) asm volatile("cp.async.wait_group 1;" ::: "memory");
            else         asm volatile("cp.async.wait_group 0;" ::: "memory");
            __syncthreads();

            const char* bb = smc + B_BASE + (idx & 1) * B_STEP;

            #pragma unroll
            for (int ks = 0; ks < 4; ks++) {
                const int kk  = ks * 16 + (lane & 3) * 2;
                const int kxg = kc * 64 + kk;

                uint32_t ah[2][4];
                #pragma unroll
                for (int mf = 0; mf < 2; mf++)
                    #pragma unroll
                    for (int j = 0; j < 4; j++) {
                        int rr = wm + mf * 16 + (lane >> 2) + (j & 1) * 8;
                        int kx = kxg + (j >> 1) * 8;
                        ah[mf][j] = *(const uint32_t*)(smc + A_H + rr * APAD_B + kx * 2);
                    }

                uint32_t bh[12][2];
                #pragma unroll
                for (int nf = 0; nf < 12; nf++) {
                    int n = wn + nf * 8 + (lane >> 2);
                    bh[nf][0] = *(const uint32_t*)(bb + n * 144 + kk * 2);
                    bh[nf][1] = *(const uint32_t*)(bb + n * 144 + (kk + 8) * 2);
                }

                #pragma unroll
                for (int mf = 0; mf < 2; mf++)
                    #pragma unroll
                    for (int nf = 0; nf < 12; nf++)
                        mma16816(acc[mf][nf], ah[mf], bh[nf]);
            }
            __syncthreads();
            if (idx + 2 < 9) prefetch(idx + 2);
        }

        const int qcol = (nt == 0);
        #pragma unroll
        for (int mf = 0; mf < 2; mf++) {
            size_t r = (size_t)mtile * 128 + wm + mf * 16 + (lane >> 2);
            #pragma unroll
            for (int nf = 0; nf < 12; nf++) {
                int c = nt * 192 + wn + nf * 8 + (lane & 3) * 2;
                float b0 = __ldg(bias + c), b1 = __ldg(bias + c + 1);
                float v0 = acc[mf][nf][0] + b0, v1 = acc[mf][nf][1] + b1;
                float w0 = acc[mf][nf][2] + b0, w1 = acc[mf][nf][3] + b1;
                if (qcol) { v0 *= QSCALE; v1 *= QSCALE; w0 *= QSCALE; w1 *= QSCALE; }
                *(uint32_t*)&g_q16[r * 576 + c] =
                    hpack(__float2half_rn(v0), __float2half_rn(v1));
                *(uint32_t*)&g_q16[(r + 8) * 576 + c] =
                    hpack(__float2half_rn(w0), __float2half_rn(w1));
            }
        }
    }
}

/* ================= K2: FUSED attention + proj =================
   128 thr/window, 2 CTAs/SM. Wp smem-resident (pad 200 fp16/row).
   Per head: attn (as R16), then oacc -> fp16 a-frags -> accumulate
   proj acc (24 n-frags x 4) against Wp k-chunk h*32. Store out + bias. */
#define WP_HALF 0
#define QH_OFF  38400                 /* 192*200 */
#define KH_OFF  (QH_OFF + 64 * 36)    /* 40704 */
#define VH_OFF  (KH_OFF + 56 * 36)    /* 42720 */
#define FUSED_HALFS (VH_OFF + 32 * 66)/* 44832 */
#define FUSED_SMEM  (FUSED_HALFS * 2) /* 89664 */

__global__ __launch_bounds__(128, 2)
void attn_proj(const float* __restrict__ proj_b, float* __restrict__ out)
{
    extern __shared__ __half sm[];
    __half* sWp = sm;
    __half* sQh = sm + QH_OFF;
    __half* sKh = sm + KH_OFF;
    __half* sVh = sm + VH_OFF;

    uint32_t sb;
    asm("{ .reg .u64 t; cvta.to.shared.u64 t, %1; cvt.u32.u64 %0, t; }" : "=r"(sb) : "l"(sm));

    const int tid  = threadIdx.x;
    const int wid  = tid >> 5, lane = tid & 31;
    const int b    = blockIdx.x;
    const int l4   = lane >> 2, lm = lane & 3;

    /* async-load Wp: 192 rows x 384 B -> pad-400 rows (group 0) */
    for (int g = tid; g < 192 * 24; g += 128) {
        int row = g / 24, c = g % 24;
        cp16(sb + row * 400 + c * 16, g_wp + row * 192 + c * 8);
    }
    asm volatile("cp.async.commit_group;" ::: "memory");

    /* zero q/k/v tile region once (pads stay zero) */
    for (int i = tid; i < FUSED_HALFS - QH_OFF; i += 128) sQh[i] = __ushort_as_half(0);

    const __half* q16 = g_q16 + (size_t)b * (NTOK * 576);
    const int r0 = wid * 16 + l4;

    float pacc[24][4];
    #pragma unroll
    for (int nf = 0; nf < 24; nf++)
        #pragma unroll
        for (int j = 0; j < 4; j++) pacc[nf][j] = 0.f;

    for (int h = 0; h < HEADS; h++) {
        __syncthreads();                       /* prev head reads done */
        /* ---- load q/k/v slices (pure fp16 copies) ---- */
        for (int idx = tid; idx < NTOK * 16; idx += 128) {
            int r = idx >> 4, c2 = (idx & 15) << 1;
            uint32_t q2 = *(const uint32_t*)&q16[r * 576 + h * 32 + c2];
            uint32_t k2 = *(const uint32_t*)&q16[r * 576 + 192 + h * 32 + c2];
            uint32_t v2 = *(const uint32_t*)&q16[r * 576 + 384 + h * 32 + c2];
            *(uint32_t*)&sQh[r * 36 + c2] = q2;
            *(uint32_t*)&sKh[r * 36 + c2] = k2;
            sVh[c2 * 66 + r]       = __ushort_as_half((unsigned short)(v2 & 0xffffu));
            sVh[(c2 + 1) * 66 + r] = __ushort_as_half((unsigned short)(v2 >> 16));
        }
        if (h == 0) asm volatile("cp.async.wait_group 0;" ::: "memory");
        __syncthreads();

        /* ---- Q a-frags ---- */
        uint32_t qh[2][4];
        #pragma unroll
        for (int kf = 0; kf < 2; kf++)
            #pragma unroll
            for (int j = 0; j < 4; j++) {
                int rr = r0 + (j & 1) * 8;
                int kx = kf * 16 + lm * 2 + (j >> 1) * 8;
                qh[kf][j] = *(const uint32_t*)&sQh[rr * 36 + kx];
            }

        /* ---- S = Q K^T ---- */
        float acc[7][4];
        #pragma unroll
        for (int nf = 0; nf < 7; nf++)
            #pragma unroll
            for (int j = 0; j < 4; j++) acc[nf][j] = 0.f;

        #pragma unroll
        for (int nf = 0; nf < 7; nf++) {
            int n = nf * 8 + l4;
            #pragma unroll
            for (int kf = 0; kf < 2; kf++) {
                uint32_t bh[2];
                bh[0] = *(const uint32_t*)&sKh[n * 36 + kf * 16 + lm * 2];
                bh[1] = *(const uint32_t*)&sKh[n * 36 + kf * 16 + lm * 2 + 8];
                mma16816(acc[nf], qh[kf], bh);
            }
        }

        /* ---- softmax ---- */
        const int ra = r0, rb = r0 + 8;
        const float* biasA = g_bias + (h * NTOK + ra) * NTOK;
        const float* biasB = g_bias + (h * NTOK + rb) * NTOK;
        float ma = -1e30f, mb = -1e30f;
        #pragma unroll
        for (int nf = 0; nf < 7; nf++) {
            int c0 = nf * 8 + lm * 2, c1 = c0 + 1;
            float ba0 = (ra < NTOK && c0 < NTOK) ? __ldg(biasA + c0) : 0.f;
            float ba1 = (ra < NTOK && c1 < NTOK) ? __ldg(biasA + c1) : 0.f;
            float bb0 = (rb < NTOK && c0 < NTOK) ? __ldg(biasB + c0) : 0.f;
            float bb1 = (rb < NTOK && c1 < NTOK) ? __ldg(biasB + c1) : 0.f;
            acc[nf][0] = (c0 < NTOK) ? acc[nf][0] + ba0 : -1e30f;
            acc[nf][1] = (c1 < NTOK) ? acc[nf][1] + ba1 : -1e30f;
            acc[nf][2] = (c0 < NTOK) ? acc[nf][2] + bb0 : -1e30f;
            acc[nf][3] = (c1 < NTOK) ? acc[nf][3] + bb1 : -1e30f;
            ma = fmaxf(ma, fmaxf(acc[nf][0], acc[nf][1]));
            mb = fmaxf(mb, fmaxf(acc[nf][2], acc[nf][3]));
        }
        ma = fmaxf(ma, __shfl_xor_sync(0xffffffffu, ma, 1));
        ma = fmaxf(ma, __shfl_xor_sync(0xffffffffu, ma, 2));
        mb = fmaxf(mb, __shfl_xor_sync(0xffffffffu, mb, 1));
        mb = fmaxf(mb, __shfl_xor_sync(0xffffffffu, mb, 2));

        float sa = 0.f, sb2 = 0.f;
        #pragma unroll
        for (int nf = 0; nf < 7; nf++) {
            acc[nf][0] = __expf(acc[nf][0] - ma);
            acc[nf][1] = __expf(acc[nf][1] - ma);
            acc[nf][2] = __expf(acc[nf][2] - mb);
            acc[nf][3] = __expf(acc[nf][3] - mb);
            sa  += acc[nf][0] + acc[nf][1];
            sb2 += acc[nf][2] + acc[nf][3];
        }
        sa  += __shfl_xor_sync(0xffffffffu, sa, 1);
        sa  += __shfl_xor_sync(0xffffffffu, sa, 2);
        sb2 += __shfl_xor_sync(0xffffffffu, sb2, 1);
        sb2 += __shfl_xor_sync(0xffffffffu, sb2, 2);
        float inva = 1.f / sa, invb = 1.f / sb2;
        #pragma unroll
        for (int nf = 0; nf < 7; nf++) {
            acc[nf][0] *= inva; acc[nf][1] *= inva;
            acc[nf][2] *= invb; acc[nf][3] *= invb;
        }

        /* ---- P a-frags (single fp16) ---- */
        uint32_t pah[4][4];
        #pragma unroll
        for (int kf = 0; kf < 4; kf++) {
            #pragma unroll
            for (int half = 0; half < 2; half++) {
                int nf = 2 * kf + half;
                if (nf < 7) {
                    pah[kf][half * 2]     = hpack(__float2half_rn(acc[nf][0]),
                                                  __float2half_rn(acc[nf][1]));
                    pah[kf][half * 2 + 1] = hpack(__float2half_rn(acc[nf][2]),
                                                  __float2half_rn(acc[nf][3]));
                } else {
                    pah[kf][half * 2] = 0u; pah[kf][half * 2 + 1] = 0u;
                }
            }
        }

        /* ---- O = P V ---- */
        float oacc[4][4];
        #pragma unroll
        for (int nf = 0; nf < 4; nf++)
            #pragma unroll
            for (int j = 0; j < 4; j++) oacc[nf][j] = 0.f;

        #pragma unroll
        for (int nf = 0; nf < 4; nf++) {
            int dh = nf * 8 + l4;
            #pragma unroll
            for (int kf = 0; kf < 4; kf++) {
                uint32_t bh[2];
                bh[0] = *(const uint32_t*)&sVh[dh * 66 + kf * 16 + lm * 2];
                bh[1] = *(const uint32_t*)&sVh[dh * 66 + kf * 16 + lm * 2 + 8];
                mma16816(oacc[nf], pah[kf], bh);
            }
        }

        /* ---- proj accumulate: oacc (C-frag) -> A-frags for k = h*32 ---- */
        uint32_t oa[2][4];
        #pragma unroll
        for (int kf = 0; kf < 2; kf++) {
            oa[kf][0] = hpack(__float2half_rn(oacc[2*kf][0]),   __float2half_rn(oacc[2*kf][1]));
            oa[kf][1] = hpack(__float2half_rn(oacc[2*kf][2]),   __float2half_rn(oacc[2*kf][3]));
            oa[kf][2] = hpack(__float2half_rn(oacc[2*kf+1][0]), __float2half_rn(oacc[2*kf+1][1]));
            oa[kf][3] = hpack(__float2half_rn(oacc[2*kf+1][2]), __float2half_rn(oacc[2*kf+1][3]));
        }
        #pragma unroll
        for (int kf = 0; kf < 2; kf++) {
            const int kw = (h * 32 + kf * 16 + lm * 2);   /* fp16 index in Wp row */
            #pragma unroll
            for (int nf = 0; nf < 24; nf++) {
                int n = nf * 8 + l4;
                uint32_t bh[2];
                bh[0] = *(const uint32_t*)&sWp[n * 200 + kw];
                bh[1] = *(const uint32_t*)&sWp[n * 200 + kw + 8];
                mma16816(pacc[nf], oa[kf], bh);
            }
        }
    }

    /* ---- store out + bias (fp32) ---- */
    const int ra = r0, rb = r0 + 8;
    if (ra < NTOK) {
        float* orow = out + ((size_t)b * NTOK + ra) * DIM;
        #pragma unroll
        for (int nf = 0; nf < 24; nf++) {
            int c = nf * 8 + lm * 2;
            float b0 = __ldg(proj_b + c), b1 = __ldg(proj_b + c + 1);
            *(float2*)(orow + c) = make_float2(pacc[nf][0] + b0, pacc[nf][1] + b1);
        }
    }
    if (rb < NTOK) {
        float* orow = out + ((size_t)b * NTOK + rb) * DIM;
        #pragma unroll
        for (int nf = 0; nf < 24; nf++) {
            int c = nf * 8 + lm * 2;
            float b0 = __ldg(proj_b + c), b1 = __ldg(proj_b + c + 1);
            *(float2*)(orow + c) = make_float2(pacc[nf][2] + b0, pacc[nf][3] + b1);
        }
    }
}

/* ================= host ================= */
extern "C" void kernel_launch(void* const* d_in, const int* in_sizes, int n_in,
                              void* d_out, int out_size)
{
    const float* x          = (const float*)d_in[0];
    const float* qkv_w      = (const float*)d_in[1];
    const float* qkv_b      = (const float*)d_in[2];
    const float* proj_w     = (const float*)d_in[3];
    const float* proj_b     = (const float*)d_in[4];
    const float* bias_table = (const float*)d_in[5];
    const int*   rel_idx    = (const int*)d_in[6];
    float*       out        = (float*)d_out;

    const int nB = in_sizes[0] / (NTOK * DIM);       /* 4096 */
    const int mt = (nB * NTOK) / 128;                /* 1568 */

    void *p_wq;
    cudaGetSymbolAddress(&p_wq, g_wq);

    cudaFuncSetAttribute(gemm_qkv,  cudaFuncAttributeMaxDynamicSharedMemorySize, GEMM_SMEM);
    cudaFuncSetAttribute(attn_proj, cudaFuncAttributeMaxDynamicSharedMemorySize, FUSED_SMEM);

    prep_kernel<<<432, 256>>>(qkv_w, proj_w, bias_table, rel_idx);

    gemm_qkv<<<mt, 256, GEMM_SMEM>>>(x, (const __half*)p_wq, qkv_b);

    attn_proj<<<nB, 128, FUSED_SMEM>>>(proj_b, out);
}